// round 10
// baseline (speedup 1.0000x reference)
#include <cuda_runtime.h>
#include <cstdint>

#define SEQ     8
#define HDIM    512
#define HOUT    256
#define LN_EPS  1e-5f
#define MAX_ROWS 65536

// Scratch: fused (node + pooled) vectors, [N, 512], tf32-rounded fp32 bits.
__device__ float g_fused[(size_t)MAX_ROWS * HDIM];
// Transposed + tf32-rounded out_W: [256, 512] (n-major, k-contiguous).
__device__ float g_Bt[(size_t)HOUT * HDIM];

// ---------------------------------------------------------------------------
// Helpers
// ---------------------------------------------------------------------------
__device__ __forceinline__ uint32_t cvt_tf32(float f) {
    uint32_t u;
    asm("cvt.rna.tf32.f32 %0, %1;" : "=r"(u) : "f"(f));
    return u;
}

__device__ __forceinline__ uint32_t smem_u32(const void* p) {
    uint32_t a;
    asm("{ .reg .u64 t; cvta.to.shared.u64 t, %1; cvt.u32.u64 %0, t; }" : "=r"(a) : "l"(p));
    return a;
}

__device__ __forceinline__ void mma_tf32(float* d, const uint32_t* a, const uint32_t* b) {
    asm volatile(
        "mma.sync.aligned.m16n8k8.row.col.f32.tf32.tf32.f32 "
        "{%0,%1,%2,%3}, {%4,%5,%6,%7}, {%8,%9}, {%0,%1,%2,%3};"
        : "+f"(d[0]), "+f"(d[1]), "+f"(d[2]), "+f"(d[3])
        : "r"(a[0]), "r"(a[1]), "r"(a[2]), "r"(a[3]), "r"(b[0]), "r"(b[1]));
}

__device__ __forceinline__ void cp_async16(uint32_t dst, const void* src) {
    asm volatile("cp.async.cg.shared.global [%0], [%1], 16;"
                 :: "r"(dst), "l"(src) : "memory");
}
#define CP_COMMIT() asm volatile("cp.async.commit_group;" ::: "memory")
#define CP_WAIT(n)  asm volatile("cp.async.wait_group %0;" :: "n"(n) : "memory")

// ---------------------------------------------------------------------------
// Kernel A (v4): LayerNorm + attention pooling — unchanged (194 µs, 78% DRAM).
// ---------------------------------------------------------------------------
__global__ __launch_bounds__(256) void ln_attn_v4_kernel(
    const float* __restrict__ x,
    const float* __restrict__ gamma,
    const float* __restrict__ beta,
    const float* __restrict__ attnW)
{
    __shared__ float s_red[8][26];
    __shared__ float s_k[8];
    __shared__ float s_K;

    const int tid  = threadIdx.x;
    const int w    = tid >> 5;
    const int lane = tid & 31;
    const size_t row = blockIdx.x;
    const int col = tid * 2;

    const float2* xr = reinterpret_cast<const float2*>(x + row * SEQ * HDIM);
    const float2 gv = *reinterpret_cast<const float2*>(gamma + col);
    const float2 wn = *reinterpret_cast<const float2*>(attnW + HDIM + col);
    const float2 gw = make_float2(gv.x * wn.x, gv.y * wn.y);

    float2 xv[SEQ];
    float vals[32];
    #pragma unroll
    for (int t = 0; t < SEQ; t++) {
        const float2 v = xr[t * (HDIM / 2) + tid];
        xv[t] = v;
        vals[t]      = v.x + v.y;
        vals[8 + t]  = v.x * v.x + v.y * v.y;
        vals[16 + t] = gw.x * v.x + gw.y * v.y;
    }
    vals[24] = gw.x + gw.y;
    #pragma unroll
    for (int j = 25; j < 32; j++) vals[j] = 0.f;

    #pragma unroll
    for (int bit = 16; bit >= 1; bit >>= 1) {
        #pragma unroll
        for (int j = 0; j < bit; j++) {
            const bool hi = (lane & bit) != 0;
            const float keep = hi ? vals[j + bit] : vals[j];
            const float send = hi ? vals[j] : vals[j + bit];
            vals[j] = keep + __shfl_xor_sync(0xffffffffu, send, bit);
        }
    }

    if (lane < 25) s_red[w][lane] = vals[0];
    __syncthreads();

    if (w == 0) {
        float v = 0.f;
        if (lane < 25) {
            #pragma unroll
            for (int wi = 0; wi < 8; wi++) v += s_red[wi][lane];
        }
        const int t = lane & 7;
        const float S  = __shfl_sync(0xffffffffu, v, t);
        const float Q  = __shfl_sync(0xffffffffu, v, 8 + t);
        const float P  = __shfl_sync(0xffffffffu, v, 16 + t);
        const float S1 = __shfl_sync(0xffffffffu, v, 24);

        const float m    = S * (1.f / HDIM);
        const float var  = Q * (1.f / HDIM) - m * m;
        const float rstd = rsqrtf(var + LN_EPS);

        float logit = (lane >= 1 && lane < 8) ? rstd * (P - m * S1) : -1e30f;

        float mx = logit;
        mx = fmaxf(mx, __shfl_xor_sync(0xffffffffu, mx, 1));
        mx = fmaxf(mx, __shfl_xor_sync(0xffffffffu, mx, 2));
        mx = fmaxf(mx, __shfl_xor_sync(0xffffffffu, mx, 4));
        const float e = __expf(logit - mx);
        float se = e;
        se += __shfl_xor_sync(0xffffffffu, se, 1);
        se += __shfl_xor_sync(0xffffffffu, se, 2);
        se += __shfl_xor_sync(0xffffffffu, se, 4);
        const float a = e / se;

        const float k = (lane == 0) ? rstd : a * rstd;
        float Km = k * m;
        Km += __shfl_xor_sync(0xffffffffu, Km, 1);
        Km += __shfl_xor_sync(0xffffffffu, Km, 2);
        Km += __shfl_xor_sync(0xffffffffu, Km, 4);

        if (lane < 8) s_k[lane] = k;
        if (lane == 0) s_K = Km;
    }
    __syncthreads();

    const float Kc = s_K;
    float2 acc = make_float2(0.f, 0.f);
    #pragma unroll
    for (int t = 0; t < SEQ; t++) {
        const float k = s_k[t];
        acc.x += k * xv[t].x;
        acc.y += k * xv[t].y;
    }
    const float2 bv = *reinterpret_cast<const float2*>(beta + col);
    uint2 o;
    o.x = cvt_tf32(gv.x * (acc.x - Kc) + 2.f * bv.x);
    o.y = cvt_tf32(gv.y * (acc.y - Kc) + 2.f * bv.y);
    *reinterpret_cast<uint2*>(&g_fused[row * HDIM + col]) = o;
}

// ---------------------------------------------------------------------------
// Transpose out_W [512,256] -> g_Bt [256,512], tf32-rounded.
// ---------------------------------------------------------------------------
__global__ __launch_bounds__(256) void transpose_B_kernel(const float* __restrict__ B) {
    __shared__ float tile[32][33];
    const int n0 = blockIdx.x * 32;
    const int k0 = blockIdx.y * 32;
    const int tx = threadIdx.x & 31;
    const int ty = threadIdx.x >> 5;
    #pragma unroll
    for (int i = 0; i < 32; i += 8)
        tile[ty + i][tx] = B[(size_t)(k0 + ty + i) * HOUT + n0 + tx];
    __syncthreads();
    #pragma unroll
    for (int i = 0; i < 32; i += 8) {
        float v = tile[tx][ty + i];
        g_Bt[(size_t)(n0 + ty + i) * HDIM + k0 + tx] = __uint_as_float(cvt_tf32(v));
    }
}

// ---------------------------------------------------------------------------
// Kernel B (v6): C = relu(A @ Bt^T + bias) via mma.sync.m16n8k8.tf32.
// CTA 128x128 with only 4 warps (128 threads), warp tile 64x64 -> fragment
// smem reads drop to 0.122 B/MAC (29% less crossbar than v4). 3-stage
// single-barrier cp.async pipeline, k-permuted LDS.128 fragments, swizzle.
// ---------------------------------------------------------------------------
#define BM 128
#define BN 128
#define BK 32
#define STAGES 3
#define A_STAGE_FLOATS (BM * BK)                     // 4096
#define B_STAGE_FLOATS (BN * BK)                     // 4096
#define STAGE_FLOATS   (A_STAGE_FLOATS + B_STAGE_FLOATS)
#define GEMM_SMEM      (STAGES * STAGE_FLOATS * 4)   // 96 KB
#define NCH            (HDIM / BK)                   // 16

__device__ __forceinline__ int swz_unit(int row, int u) {
    return row * 8 + (u ^ ((row & 1) << 2));
}

__global__ __launch_bounds__(128, 2) void gemm_v6_kernel(
    const float* __restrict__ bias,
    float* __restrict__ C)
{
    extern __shared__ float smem[];

    const int tid  = threadIdx.x;
    const int lane = tid & 31;
    const int wid  = tid >> 5;            // 0..3
    const int warp_m = wid & 1;           // 0..1 -> M offset *64
    const int warp_n = wid >> 1;          // 0..1 -> N offset *64
    const int g  = lane >> 2;             // 0..7
    const int tg = lane & 3;              // 0..3

    const int bn = blockIdx.x;            // 0..1
    const int bm = blockIdx.y;

    const float* Ag = g_fused + (size_t)bm * BM * HDIM;
    const float* Bg = g_Bt + (size_t)bn * BN * HDIM;

    const uint32_t smem_base = smem_u32(smem);

    float acc[4][8][4];
    #pragma unroll
    for (int mt = 0; mt < 4; mt++)
        #pragma unroll
        for (int nt = 0; nt < 8; nt++)
            #pragma unroll
            for (int i = 0; i < 4; i++) acc[mt][nt][i] = 0.f;

    // Staging: 128 threads; thread t owns row t of both tiles (8 units each).
    auto stage_chunk = [&](int kchunk, int st) {
        const uint32_t sA = smem_base + (uint32_t)(st * STAGE_FLOATS) * 4u;
        const uint32_t sB = sA + A_STAGE_FLOATS * 4u;
        const float* srcA = Ag + (size_t)tid * HDIM + kchunk * BK;
        const float* srcB = Bg + (size_t)tid * HDIM + kchunk * BK;
        #pragma unroll
        for (int j = 0; j < 8; j++)
            cp_async16(sA + (uint32_t)swz_unit(tid, j) * 16u, srcA + j * 4);
        #pragma unroll
        for (int j = 0; j < 8; j++)
            cp_async16(sB + (uint32_t)swz_unit(tid, j) * 16u, srcB + j * 4);
    };

    // Prologue: stage chunks 0,1.
    stage_chunk(0, 0); CP_COMMIT();
    stage_chunk(1, 1); CP_COMMIT();

    int cur = 0, nxt = 2;   // slot of chunk k; slot to refill with chunk k+2
    #pragma unroll 1
    for (int k = 0; k < NCH; k++) {
        CP_WAIT(1);
        __syncthreads();   // slot 'nxt' fully consumed in iteration k-1

        if (k + 2 < NCH) stage_chunk(k + 2, nxt);
        CP_COMMIT();

        const float* Abuf = smem + cur * STAGE_FLOATS;
        const float* Bbuf = Abuf + A_STAGE_FLOATS;

        #pragma unroll
        for (int s = 0; s < 2; s++) {
            uint32_t af[8][4];                 // [mt*2 + h][slot]
            #pragma unroll
            for (int mt = 0; mt < 4; mt++) {
                #pragma unroll
                for (int h = 0; h < 2; h++) {
                    const int r = warp_m * 64 + mt * 16 + g + h * 8;
                    const float4 v = *reinterpret_cast<const float4*>(
                        Abuf + swz_unit(r, s * 4 + tg) * 4);
                    af[mt * 2 + h][0] = __float_as_uint(v.x);
                    af[mt * 2 + h][1] = __float_as_uint(v.y);
                    af[mt * 2 + h][2] = __float_as_uint(v.z);
                    af[mt * 2 + h][3] = __float_as_uint(v.w);
                }
            }
            #pragma unroll
            for (int half = 0; half < 2; half++) {
                uint32_t bf[4][4];
                #pragma unroll
                for (int q = 0; q < 4; q++) {
                    const int n = warp_n * 64 + (half * 4 + q) * 8 + g;
                    const float4 v = *reinterpret_cast<const float4*>(
                        Bbuf + swz_unit(n, s * 4 + tg) * 4);
                    bf[q][0] = __float_as_uint(v.x);
                    bf[q][1] = __float_as_uint(v.y);
                    bf[q][2] = __float_as_uint(v.z);
                    bf[q][3] = __float_as_uint(v.w);
                }
                #pragma unroll
                for (int mt = 0; mt < 4; mt++) {
                    #pragma unroll
                    for (int q = 0; q < 4; q++) {
                        const int nt = half * 4 + q;
                        uint32_t a0[4] = { af[mt*2][0], af[mt*2+1][0],
                                           af[mt*2][1], af[mt*2+1][1] };
                        uint32_t b0[2] = { bf[q][0], bf[q][1] };
                        mma_tf32(acc[mt][nt], a0, b0);
                        uint32_t a1[4] = { af[mt*2][2], af[mt*2+1][2],
                                           af[mt*2][3], af[mt*2+1][3] };
                        uint32_t b1[2] = { bf[q][2], bf[q][3] };
                        mma_tf32(acc[mt][nt], a1, b1);
                    }
                }
            }
        }

        cur = (cur == 2) ? 0 : cur + 1;
        nxt = (nxt == 2) ? 0 : nxt + 1;
    }

    // Epilogue: bias + relu.
    const int row_base = bm * BM + warp_m * 64;
    const int col_base = bn * BN + warp_n * 64;
    #pragma unroll
    for (int mt = 0; mt < 4; mt++) {
        #pragma unroll
        for (int nt = 0; nt < 8; nt++) {
            const int r0 = row_base + mt * 16 + g;
            const int c0 = col_base + nt * 8 + 2 * tg;
            const float2 bb = *reinterpret_cast<const float2*>(bias + c0);
            float2 o0, o1;
            o0.x = fmaxf(acc[mt][nt][0] + bb.x, 0.f);
            o0.y = fmaxf(acc[mt][nt][1] + bb.y, 0.f);
            o1.x = fmaxf(acc[mt][nt][2] + bb.x, 0.f);
            o1.y = fmaxf(acc[mt][nt][3] + bb.y, 0.f);
            *reinterpret_cast<float2*>(C + (size_t)r0 * HOUT + c0) = o0;
            *reinterpret_cast<float2*>(C + (size_t)(r0 + 8) * HOUT + c0) = o1;
        }
    }
}

// ---------------------------------------------------------------------------
extern "C" void kernel_launch(void* const* d_in, const int* in_sizes, int n_in,
                              void* d_out, int out_size) {
    const float* x     = (const float*)d_in[0];   // [N, 8, 512]
    const float* gamma = (const float*)d_in[1];   // [512]
    const float* beta  = (const float*)d_in[2];   // [512]
    const float* attnW = (const float*)d_in[3];   // [1024, 1]
    // d_in[4] = attn_b: cancels in softmax.
    const float* outW  = (const float*)d_in[5];   // [512, 256]
    const float* outb  = (const float*)d_in[6];   // [256]
    float* out = (float*)d_out;                   // [N, 256]

    const int n = in_sizes[0] / (SEQ * HDIM);

    cudaFuncSetAttribute(gemm_v6_kernel,
                         cudaFuncAttributeMaxDynamicSharedMemorySize, GEMM_SMEM);

    ln_attn_v4_kernel<<<n, 256>>>(x, gamma, beta, attnW);
    transpose_B_kernel<<<dim3(HOUT / 32, HDIM / 32), 256>>>(outW);

    dim3 grid(HOUT / BN, n / BM);
    gemm_v6_kernel<<<grid, 128, GEMM_SMEM>>>(outb, out);
}

// round 11
// speedup vs baseline: 1.2110x; 1.2110x over previous
#include <cuda_runtime.h>
#include <cstdint>

#define SEQ     8
#define HDIM    512
#define HOUT    256
#define LN_EPS  1e-5f
#define MAX_ROWS 65536

// Scratch: fused (node + pooled) vectors, [N, 512], tf32-rounded fp32 bits.
__device__ float g_fused[(size_t)MAX_ROWS * HDIM];
// Transposed + tf32-rounded out_W: [256, 512] (n-major, k-contiguous).
__device__ float g_Bt[(size_t)HOUT * HDIM];

// ---------------------------------------------------------------------------
// Helpers
// ---------------------------------------------------------------------------
__device__ __forceinline__ uint32_t cvt_tf32(float f) {
    uint32_t u;
    asm("cvt.rna.tf32.f32 %0, %1;" : "=r"(u) : "f"(f));
    return u;
}

__device__ __forceinline__ uint32_t smem_u32(const void* p) {
    uint32_t a;
    asm("{ .reg .u64 t; cvta.to.shared.u64 t, %1; cvt.u32.u64 %0, t; }" : "=r"(a) : "l"(p));
    return a;
}

__device__ __forceinline__ void mma_tf32(float* d, const uint32_t* a, const uint32_t* b) {
    asm volatile(
        "mma.sync.aligned.m16n8k8.row.col.f32.tf32.tf32.f32 "
        "{%0,%1,%2,%3}, {%4,%5,%6,%7}, {%8,%9}, {%0,%1,%2,%3};"
        : "+f"(d[0]), "+f"(d[1]), "+f"(d[2]), "+f"(d[3])
        : "r"(a[0]), "r"(a[1]), "r"(a[2]), "r"(a[3]), "r"(b[0]), "r"(b[1]));
}

__device__ __forceinline__ void cp_async16(uint32_t dst, const void* src) {
    asm volatile("cp.async.cg.shared.global [%0], [%1], 16;"
                 :: "r"(dst), "l"(src) : "memory");
}
#define CP_COMMIT() asm volatile("cp.async.commit_group;" ::: "memory")
#define CP_WAIT(n)  asm volatile("cp.async.wait_group %0;" :: "n"(n) : "memory")

// ---------------------------------------------------------------------------
// Kernel A (v4): LayerNorm + attention pooling — frozen (194-197 µs, 77% DRAM).
// ---------------------------------------------------------------------------
__global__ __launch_bounds__(256) void ln_attn_v4_kernel(
    const float* __restrict__ x,
    const float* __restrict__ gamma,
    const float* __restrict__ beta,
    const float* __restrict__ attnW)
{
    __shared__ float s_red[8][26];
    __shared__ float s_k[8];
    __shared__ float s_K;

    const int tid  = threadIdx.x;
    const int w    = tid >> 5;
    const int lane = tid & 31;
    const size_t row = blockIdx.x;
    const int col = tid * 2;

    const float2* xr = reinterpret_cast<const float2*>(x + row * SEQ * HDIM);
    const float2 gv = *reinterpret_cast<const float2*>(gamma + col);
    const float2 wn = *reinterpret_cast<const float2*>(attnW + HDIM + col);
    const float2 gw = make_float2(gv.x * wn.x, gv.y * wn.y);

    float2 xv[SEQ];
    float vals[32];
    #pragma unroll
    for (int t = 0; t < SEQ; t++) {
        const float2 v = xr[t * (HDIM / 2) + tid];
        xv[t] = v;
        vals[t]      = v.x + v.y;
        vals[8 + t]  = v.x * v.x + v.y * v.y;
        vals[16 + t] = gw.x * v.x + gw.y * v.y;
    }
    vals[24] = gw.x + gw.y;
    #pragma unroll
    for (int j = 25; j < 32; j++) vals[j] = 0.f;

    #pragma unroll
    for (int bit = 16; bit >= 1; bit >>= 1) {
        #pragma unroll
        for (int j = 0; j < bit; j++) {
            const bool hi = (lane & bit) != 0;
            const float keep = hi ? vals[j + bit] : vals[j];
            const float send = hi ? vals[j] : vals[j + bit];
            vals[j] = keep + __shfl_xor_sync(0xffffffffu, send, bit);
        }
    }

    if (lane < 25) s_red[w][lane] = vals[0];
    __syncthreads();

    if (w == 0) {
        float v = 0.f;
        if (lane < 25) {
            #pragma unroll
            for (int wi = 0; wi < 8; wi++) v += s_red[wi][lane];
        }
        const int t = lane & 7;
        const float S  = __shfl_sync(0xffffffffu, v, t);
        const float Q  = __shfl_sync(0xffffffffu, v, 8 + t);
        const float P  = __shfl_sync(0xffffffffu, v, 16 + t);
        const float S1 = __shfl_sync(0xffffffffu, v, 24);

        const float m    = S * (1.f / HDIM);
        const float var  = Q * (1.f / HDIM) - m * m;
        const float rstd = rsqrtf(var + LN_EPS);

        float logit = (lane >= 1 && lane < 8) ? rstd * (P - m * S1) : -1e30f;

        float mx = logit;
        mx = fmaxf(mx, __shfl_xor_sync(0xffffffffu, mx, 1));
        mx = fmaxf(mx, __shfl_xor_sync(0xffffffffu, mx, 2));
        mx = fmaxf(mx, __shfl_xor_sync(0xffffffffu, mx, 4));
        const float e = __expf(logit - mx);
        float se = e;
        se += __shfl_xor_sync(0xffffffffu, se, 1);
        se += __shfl_xor_sync(0xffffffffu, se, 2);
        se += __shfl_xor_sync(0xffffffffu, se, 4);
        const float a = e / se;

        const float k = (lane == 0) ? rstd : a * rstd;
        float Km = k * m;
        Km += __shfl_xor_sync(0xffffffffu, Km, 1);
        Km += __shfl_xor_sync(0xffffffffu, Km, 2);
        Km += __shfl_xor_sync(0xffffffffu, Km, 4);

        if (lane < 8) s_k[lane] = k;
        if (lane == 0) s_K = Km;
    }
    __syncthreads();

    const float Kc = s_K;
    float2 acc = make_float2(0.f, 0.f);
    #pragma unroll
    for (int t = 0; t < SEQ; t++) {
        const float k = s_k[t];
        acc.x += k * xv[t].x;
        acc.y += k * xv[t].y;
    }
    const float2 bv = *reinterpret_cast<const float2*>(beta + col);
    uint2 o;
    o.x = cvt_tf32(gv.x * (acc.x - Kc) + 2.f * bv.x);
    o.y = cvt_tf32(gv.y * (acc.y - Kc) + 2.f * bv.y);
    *reinterpret_cast<uint2*>(&g_fused[row * HDIM + col]) = o;
}

// ---------------------------------------------------------------------------
// Transpose out_W [512,256] -> g_Bt [256,512], tf32-rounded.
// ---------------------------------------------------------------------------
__global__ __launch_bounds__(256) void transpose_B_kernel(const float* __restrict__ B) {
    __shared__ float tile[32][33];
    const int n0 = blockIdx.x * 32;
    const int k0 = blockIdx.y * 32;
    const int tx = threadIdx.x & 31;
    const int ty = threadIdx.x >> 5;
    #pragma unroll
    for (int i = 0; i < 32; i += 8)
        tile[ty + i][tx] = B[(size_t)(k0 + ty + i) * HOUT + n0 + tx];
    __syncthreads();
    #pragma unroll
    for (int i = 0; i < 32; i += 8) {
        float v = tile[tx][ty + i];
        g_Bt[(size_t)(n0 + ty + i) * HDIM + k0 + tx] = __uint_as_float(cvt_tf32(v));
    }
}

// ---------------------------------------------------------------------------
// Kernel B (v4r): C = relu(A @ Bt^T + bias) via mma.sync.m16n8k8.tf32.
// Exact revert to the proven v4 config (CTA 128x128, 8 warps 4x2, warp tile
// 32x64, BK=32, 3-stage single-barrier cp.async) PLUS reversed bm traversal:
// GEMM reads the most-recently-written g_fused rows first, so a large
// fraction of the A read hits L2 left warm by ln_attn.
// ---------------------------------------------------------------------------
#define BM 128
#define BN 128
#define BK 32
#define STAGES 3
#define A_STAGE_FLOATS (BM * BK)
#define B_STAGE_FLOATS (BN * BK)
#define STAGE_FLOATS   (A_STAGE_FLOATS + B_STAGE_FLOATS)
#define GEMM_SMEM      (STAGES * STAGE_FLOATS * 4)
#define NCH            (HDIM / BK)     // 16

__device__ __forceinline__ int swz_unit(int row, int u) {
    return row * 8 + (u ^ ((row & 1) << 2));
}

__global__ __launch_bounds__(256, 2) void gemm_v4r_kernel(
    const float* __restrict__ bias,
    float* __restrict__ C)
{
    extern __shared__ float smem[];

    const int tid  = threadIdx.x;
    const int lane = tid & 31;
    const int wid  = tid >> 5;
    const int warp_m = wid & 3;
    const int warp_n = wid >> 2;
    const int g  = lane >> 2;
    const int tg = lane & 3;

    const int bn = blockIdx.x;
    const int bm = (int)(gridDim.y - 1) - (int)blockIdx.y;   // reversed: newest rows first

    const float* Ag = g_fused + (size_t)bm * BM * HDIM;
    const float* Bg = g_Bt + (size_t)bn * BN * HDIM;

    const uint32_t smem_base = smem_u32(smem);

    const int st_row = tid >> 1;
    const int st_ub  = (tid & 1) * 4;

    float acc[2][8][4];
    #pragma unroll
    for (int mt = 0; mt < 2; mt++)
        #pragma unroll
        for (int nt = 0; nt < 8; nt++)
            #pragma unroll
            for (int i = 0; i < 4; i++) acc[mt][nt][i] = 0.f;

    auto stage_chunk = [&](int kchunk, int st) {
        const uint32_t sA = smem_base + (uint32_t)(st * STAGE_FLOATS) * 4u;
        const uint32_t sB = sA + A_STAGE_FLOATS * 4u;
        const float* srcA = Ag + (size_t)st_row * HDIM + kchunk * BK + st_ub * 4;
        const float* srcB = Bg + (size_t)st_row * HDIM + kchunk * BK + st_ub * 4;
        #pragma unroll
        for (int j = 0; j < 4; j++)
            cp_async16(sA + (uint32_t)swz_unit(st_row, st_ub + j) * 16u, srcA + j * 4);
        #pragma unroll
        for (int j = 0; j < 4; j++)
            cp_async16(sB + (uint32_t)swz_unit(st_row, st_ub + j) * 16u, srcB + j * 4);
    };

    // Prologue: stage chunks 0,1 (STAGES-1 groups in flight).
    stage_chunk(0, 0); CP_COMMIT();
    stage_chunk(1, 1); CP_COMMIT();

    #pragma unroll
    for (int k = 0; k < NCH; k++) {
        const int cur = k % STAGES;

        CP_WAIT(1);
        __syncthreads();   // slot (k+2)%3 fully consumed in iteration k-1

        if (k + 2 < NCH) stage_chunk(k + 2, (k + 2) % STAGES);
        CP_COMMIT();

        const float* Abuf = smem + cur * STAGE_FLOATS;
        const float* Bbuf = Abuf + A_STAGE_FLOATS;

        #pragma unroll
        for (int s = 0; s < 2; s++) {
            uint32_t af[4][4];
            #pragma unroll
            for (int mt = 0; mt < 2; mt++) {
                #pragma unroll
                for (int h = 0; h < 2; h++) {
                    const int r = warp_m * 32 + mt * 16 + g + h * 8;
                    const float4 v = *reinterpret_cast<const float4*>(
                        Abuf + swz_unit(r, s * 4 + tg) * 4);
                    af[mt * 2 + h][0] = __float_as_uint(v.x);
                    af[mt * 2 + h][1] = __float_as_uint(v.y);
                    af[mt * 2 + h][2] = __float_as_uint(v.z);
                    af[mt * 2 + h][3] = __float_as_uint(v.w);
                }
            }
            #pragma unroll
            for (int half = 0; half < 2; half++) {
                uint32_t bf[4][4];
                #pragma unroll
                for (int q = 0; q < 4; q++) {
                    const int n = warp_n * 64 + (half * 4 + q) * 8 + g;
                    const float4 v = *reinterpret_cast<const float4*>(
                        Bbuf + swz_unit(n, s * 4 + tg) * 4);
                    bf[q][0] = __float_as_uint(v.x);
                    bf[q][1] = __float_as_uint(v.y);
                    bf[q][2] = __float_as_uint(v.z);
                    bf[q][3] = __float_as_uint(v.w);
                }
                #pragma unroll
                for (int mt = 0; mt < 2; mt++) {
                    #pragma unroll
                    for (int q = 0; q < 4; q++) {
                        const int nt = half * 4 + q;
                        uint32_t a0[4] = { af[mt*2][0], af[mt*2+1][0],
                                           af[mt*2][1], af[mt*2+1][1] };
                        uint32_t b0[2] = { bf[q][0], bf[q][1] };
                        mma_tf32(acc[mt][nt], a0, b0);
                        uint32_t a1[4] = { af[mt*2][2], af[mt*2+1][2],
                                           af[mt*2][3], af[mt*2+1][3] };
                        uint32_t b1[2] = { bf[q][2], bf[q][3] };
                        mma_tf32(acc[mt][nt], a1, b1);
                    }
                }
            }
        }
    }

    // Epilogue: bias + relu.
    const int row_base = bm * BM + warp_m * 32;
    const int col_base = bn * BN + warp_n * 64;
    #pragma unroll
    for (int mt = 0; mt < 2; mt++) {
        #pragma unroll
        for (int nt = 0; nt < 8; nt++) {
            const int r0 = row_base + mt * 16 + g;
            const int c0 = col_base + nt * 8 + 2 * tg;
            const float2 bb = *reinterpret_cast<const float2*>(bias + c0);
            float2 o0, o1;
            o0.x = fmaxf(acc[mt][nt][0] + bb.x, 0.f);
            o0.y = fmaxf(acc[mt][nt][1] + bb.y, 0.f);
            o1.x = fmaxf(acc[mt][nt][2] + bb.x, 0.f);
            o1.y = fmaxf(acc[mt][nt][3] + bb.y, 0.f);
            *reinterpret_cast<float2*>(C + (size_t)r0 * HOUT + c0) = o0;
            *reinterpret_cast<float2*>(C + (size_t)(r0 + 8) * HOUT + c0) = o1;
        }
    }
}

// ---------------------------------------------------------------------------
extern "C" void kernel_launch(void* const* d_in, const int* in_sizes, int n_in,
                              void* d_out, int out_size) {
    const float* x     = (const float*)d_in[0];   // [N, 8, 512]
    const float* gamma = (const float*)d_in[1];   // [512]
    const float* beta  = (const float*)d_in[2];   // [512]
    const float* attnW = (const float*)d_in[3];   // [1024, 1]
    // d_in[4] = attn_b: cancels in softmax.
    const float* outW  = (const float*)d_in[5];   // [512, 256]
    const float* outb  = (const float*)d_in[6];   // [256]
    float* out = (float*)d_out;                   // [N, 256]

    const int n = in_sizes[0] / (SEQ * HDIM);

    cudaFuncSetAttribute(gemm_v4r_kernel,
                         cudaFuncAttributeMaxDynamicSharedMemorySize, GEMM_SMEM);

    transpose_B_kernel<<<dim3(HOUT / 32, HDIM / 32), 256>>>(outW);
    ln_attn_v4_kernel<<<n, 256>>>(x, gamma, beta, attnW);

    dim3 grid(HOUT / BN, n / BM);
    gemm_v4r_kernel<<<grid, 256, GEMM_SMEM>>>(outb, out);
}

// round 12
// speedup vs baseline: 1.5151x; 1.2511x over previous
#include <cuda_runtime.h>
#include <cuda_fp16.h>
#include <cstdint>

#define SEQ     8
#define HDIM    512
#define HOUT    256
#define LN_EPS  1e-5f
#define MAX_ROWS 65536

// Scratch: fused (node + pooled) vectors, [N, 512], fp16.
__device__ __half g_fused[(size_t)MAX_ROWS * HDIM];
// Transposed + fp16-rounded out_W: [256, 512] (n-major, k-contiguous).
__device__ __half g_Bt[(size_t)HOUT * HDIM];

// ---------------------------------------------------------------------------
// Helpers
// ---------------------------------------------------------------------------
__device__ __forceinline__ uint32_t smem_u32(const void* p) {
    uint32_t a;
    asm("{ .reg .u64 t; cvta.to.shared.u64 t, %1; cvt.u32.u64 %0, t; }" : "=r"(a) : "l"(p));
    return a;
}

__device__ __forceinline__ void mma_fp16(float* d, const uint32_t* a, const uint32_t* b) {
    asm volatile(
        "mma.sync.aligned.m16n8k16.row.col.f32.f16.f16.f32 "
        "{%0,%1,%2,%3}, {%4,%5,%6,%7}, {%8,%9}, {%0,%1,%2,%3};"
        : "+f"(d[0]), "+f"(d[1]), "+f"(d[2]), "+f"(d[3])
        : "r"(a[0]), "r"(a[1]), "r"(a[2]), "r"(a[3]), "r"(b[0]), "r"(b[1]));
}

__device__ __forceinline__ void cp_async16(uint32_t dst, const void* src) {
    asm volatile("cp.async.cg.shared.global [%0], [%1], 16;"
                 :: "r"(dst), "l"(src) : "memory");
}
#define CP_COMMIT() asm volatile("cp.async.commit_group;" ::: "memory")
#define CP_WAIT(n)  asm volatile("cp.async.wait_group %0;" :: "n"(n) : "memory")

// ---------------------------------------------------------------------------
// Kernel A (v5): LayerNorm + attention pooling — v4 math, fp16 output.
// ---------------------------------------------------------------------------
__global__ __launch_bounds__(256) void ln_attn_v5_kernel(
    const float* __restrict__ x,
    const float* __restrict__ gamma,
    const float* __restrict__ beta,
    const float* __restrict__ attnW)
{
    __shared__ float s_red[8][26];
    __shared__ float s_k[8];
    __shared__ float s_K;

    const int tid  = threadIdx.x;
    const int w    = tid >> 5;
    const int lane = tid & 31;
    const size_t row = blockIdx.x;
    const int col = tid * 2;

    const float2* xr = reinterpret_cast<const float2*>(x + row * SEQ * HDIM);
    const float2 gv = *reinterpret_cast<const float2*>(gamma + col);
    const float2 wn = *reinterpret_cast<const float2*>(attnW + HDIM + col);
    const float2 gw = make_float2(gv.x * wn.x, gv.y * wn.y);

    float2 xv[SEQ];
    float vals[32];
    #pragma unroll
    for (int t = 0; t < SEQ; t++) {
        const float2 v = xr[t * (HDIM / 2) + tid];
        xv[t] = v;
        vals[t]      = v.x + v.y;
        vals[8 + t]  = v.x * v.x + v.y * v.y;
        vals[16 + t] = gw.x * v.x + gw.y * v.y;
    }
    vals[24] = gw.x + gw.y;
    #pragma unroll
    for (int j = 25; j < 32; j++) vals[j] = 0.f;

    #pragma unroll
    for (int bit = 16; bit >= 1; bit >>= 1) {
        #pragma unroll
        for (int j = 0; j < bit; j++) {
            const bool hi = (lane & bit) != 0;
            const float keep = hi ? vals[j + bit] : vals[j];
            const float send = hi ? vals[j] : vals[j + bit];
            vals[j] = keep + __shfl_xor_sync(0xffffffffu, send, bit);
        }
    }

    if (lane < 25) s_red[w][lane] = vals[0];
    __syncthreads();

    if (w == 0) {
        float v = 0.f;
        if (lane < 25) {
            #pragma unroll
            for (int wi = 0; wi < 8; wi++) v += s_red[wi][lane];
        }
        const int t = lane & 7;
        const float S  = __shfl_sync(0xffffffffu, v, t);
        const float Q  = __shfl_sync(0xffffffffu, v, 8 + t);
        const float P  = __shfl_sync(0xffffffffu, v, 16 + t);
        const float S1 = __shfl_sync(0xffffffffu, v, 24);

        const float m    = S * (1.f / HDIM);
        const float var  = Q * (1.f / HDIM) - m * m;
        const float rstd = rsqrtf(var + LN_EPS);

        float logit = (lane >= 1 && lane < 8) ? rstd * (P - m * S1) : -1e30f;

        float mx = logit;
        mx = fmaxf(mx, __shfl_xor_sync(0xffffffffu, mx, 1));
        mx = fmaxf(mx, __shfl_xor_sync(0xffffffffu, mx, 2));
        mx = fmaxf(mx, __shfl_xor_sync(0xffffffffu, mx, 4));
        const float e = __expf(logit - mx);
        float se = e;
        se += __shfl_xor_sync(0xffffffffu, se, 1);
        se += __shfl_xor_sync(0xffffffffu, se, 2);
        se += __shfl_xor_sync(0xffffffffu, se, 4);
        const float a = e / se;

        const float k = (lane == 0) ? rstd : a * rstd;
        float Km = k * m;
        Km += __shfl_xor_sync(0xffffffffu, Km, 1);
        Km += __shfl_xor_sync(0xffffffffu, Km, 2);
        Km += __shfl_xor_sync(0xffffffffu, Km, 4);

        if (lane < 8) s_k[lane] = k;
        if (lane == 0) s_K = Km;
    }
    __syncthreads();

    const float Kc = s_K;
    float2 acc = make_float2(0.f, 0.f);
    #pragma unroll
    for (int t = 0; t < SEQ; t++) {
        const float k = s_k[t];
        acc.x += k * xv[t].x;
        acc.y += k * xv[t].y;
    }
    const float2 bv = *reinterpret_cast<const float2*>(beta + col);
    const __half2 o = __floats2half2_rn(gv.x * (acc.x - Kc) + 2.f * bv.x,
                                        gv.y * (acc.y - Kc) + 2.f * bv.y);
    reinterpret_cast<__half2*>(g_fused)[row * (HDIM / 2) + tid] = o;
}

// ---------------------------------------------------------------------------
// Transpose out_W [512,256] -> g_Bt [256,512] fp16.
// ---------------------------------------------------------------------------
__global__ __launch_bounds__(256) void transpose_B_kernel(const float* __restrict__ B) {
    __shared__ float tile[32][33];
    const int n0 = blockIdx.x * 32;
    const int k0 = blockIdx.y * 32;
    const int tx = threadIdx.x & 31;
    const int ty = threadIdx.x >> 5;
    #pragma unroll
    for (int i = 0; i < 32; i += 8)
        tile[ty + i][tx] = B[(size_t)(k0 + ty + i) * HOUT + n0 + tx];
    __syncthreads();
    #pragma unroll
    for (int i = 0; i < 32; i += 8) {
        g_Bt[(size_t)(n0 + ty + i) * HDIM + k0 + tx] = __float2half_rn(tile[tx][ty + i]);
    }
}

// ---------------------------------------------------------------------------
// Kernel B (v7): C = relu(A @ Bt^T + bias) via mma.sync.m16n8k16.f16 (fp32 acc).
// CTA 128x128, 8 warps 4x2, warp tile 32x64, BK=32 halfs, 3-stage
// single-barrier cp.async pipeline. K-permuted fragments: each thread's
// LDS.128 (8 halfs at physical k=8*tg) feeds both k-groups; identical
// logical->physical map on A and B keeps dot products exact. 64 B rows make
// fragment fetches conflict-free without swizzle (row parity alternates
// within each 8-lane phase octet).
// ---------------------------------------------------------------------------
#define BM 128
#define BN 128
#define BKH 32                                    // halfs per chunk
#define STAGES 3
#define A_STAGE_BYTES (BM * BKH * 2)              // 8 KB
#define B_STAGE_BYTES (BN * BKH * 2)              // 8 KB
#define STAGE_BYTES   (A_STAGE_BYTES + B_STAGE_BYTES)
#define GEMM_SMEM     (STAGES * STAGE_BYTES)      // 48 KB
#define NCH           (HDIM / BKH)                // 16

__global__ __launch_bounds__(256, 2) void gemm_fp16_kernel(
    const float* __restrict__ bias,
    float* __restrict__ C)
{
    extern __shared__ char smem[];

    const int tid  = threadIdx.x;
    const int lane = tid & 31;
    const int wid  = tid >> 5;
    const int warp_m = wid & 3;            // 0..3 -> M offset *32
    const int warp_n = wid >> 2;           // 0..1 -> N offset *64
    const int g  = lane >> 2;              // 0..7
    const int tg = lane & 3;               // 0..3

    const int bn = blockIdx.x;
    const int bm = (int)(gridDim.y - 1) - (int)blockIdx.y;   // newest rows first

    const __half* Ag = g_fused + (size_t)bm * BM * HDIM;
    const __half* Bg = g_Bt + (size_t)bn * BN * HDIM;

    const uint32_t smem_base = smem_u32(smem);

    // Staging: thread t -> row t>>1, 16B units (t&1)*2 + {0,1}. Row = 4 units.
    const int st_row = tid >> 1;
    const int st_u   = (tid & 1) * 2;

    float acc[2][8][4];
    #pragma unroll
    for (int mt = 0; mt < 2; mt++)
        #pragma unroll
        for (int nt = 0; nt < 8; nt++)
            #pragma unroll
            for (int i = 0; i < 4; i++) acc[mt][nt][i] = 0.f;

    auto stage_chunk = [&](int kchunk, int st) {
        const uint32_t sA = smem_base + (uint32_t)(st * STAGE_BYTES);
        const uint32_t sB = sA + A_STAGE_BYTES;
        const __half* srcA = Ag + (size_t)st_row * HDIM + kchunk * BKH + st_u * 8;
        const __half* srcB = Bg + (size_t)st_row * HDIM + kchunk * BKH + st_u * 8;
        #pragma unroll
        for (int j = 0; j < 2; j++)
            cp_async16(sA + (uint32_t)(st_row * 4 + st_u + j) * 16u, srcA + j * 8);
        #pragma unroll
        for (int j = 0; j < 2; j++)
            cp_async16(sB + (uint32_t)(st_row * 4 + st_u + j) * 16u, srcB + j * 8);
    };

    stage_chunk(0, 0); CP_COMMIT();
    stage_chunk(1, 1); CP_COMMIT();

    #pragma unroll
    for (int k = 0; k < NCH; k++) {
        const int cur = k % STAGES;

        CP_WAIT(1);
        __syncthreads();   // slot (k+2)%3 fully consumed in iteration k-1

        if (k + 2 < NCH) stage_chunk(k + 2, (k + 2) % STAGES);
        CP_COMMIT();

        const char* Abuf = smem + cur * STAGE_BYTES;
        const char* Bbuf = Abuf + A_STAGE_BYTES;

        // A fragments: 4 LDS.128 -> aw[mt][h][4 regs of half2]
        uint32_t aw[2][2][4];
        #pragma unroll
        for (int mt = 0; mt < 2; mt++) {
            #pragma unroll
            for (int h = 0; h < 2; h++) {
                const int r = warp_m * 32 + mt * 16 + g + h * 8;
                const uint4 v = *reinterpret_cast<const uint4*>(
                    Abuf + (r * 4 + tg) * 16);
                aw[mt][h][0] = v.x; aw[mt][h][1] = v.y;
                aw[mt][h][2] = v.z; aw[mt][h][3] = v.w;
            }
        }
        #pragma unroll
        for (int half = 0; half < 2; half++) {
            uint32_t bw[4][4];
            #pragma unroll
            for (int q = 0; q < 4; q++) {
                const int n = warp_n * 64 + (half * 4 + q) * 8 + g;
                const uint4 v = *reinterpret_cast<const uint4*>(
                    Bbuf + (n * 4 + tg) * 16);
                bw[q][0] = v.x; bw[q][1] = v.y; bw[q][2] = v.z; bw[q][3] = v.w;
            }
            #pragma unroll
            for (int grp = 0; grp < 2; grp++) {
                #pragma unroll
                for (int mt = 0; mt < 2; mt++) {
                    #pragma unroll
                    for (int q = 0; q < 4; q++) {
                        const int nt = half * 4 + q;
                        uint32_t a[4] = { aw[mt][0][grp * 2 + 0],
                                          aw[mt][1][grp * 2 + 0],
                                          aw[mt][0][grp * 2 + 1],
                                          aw[mt][1][grp * 2 + 1] };
                        uint32_t b[2] = { bw[q][grp * 2 + 0],
                                          bw[q][grp * 2 + 1] };
                        mma_fp16(acc[mt][nt], a, b);
                    }
                }
            }
        }
    }

    // Epilogue: bias + relu.
    const int row_base = bm * BM + warp_m * 32;
    const int col_base = bn * BN + warp_n * 64;
    #pragma unroll
    for (int mt = 0; mt < 2; mt++) {
        #pragma unroll
        for (int nt = 0; nt < 8; nt++) {
            const int r0 = row_base + mt * 16 + g;
            const int c0 = col_base + nt * 8 + 2 * tg;
            const float2 bb = *reinterpret_cast<const float2*>(bias + c0);
            float2 o0, o1;
            o0.x = fmaxf(acc[mt][nt][0] + bb.x, 0.f);
            o0.y = fmaxf(acc[mt][nt][1] + bb.y, 0.f);
            o1.x = fmaxf(acc[mt][nt][2] + bb.x, 0.f);
            o1.y = fmaxf(acc[mt][nt][3] + bb.y, 0.f);
            *reinterpret_cast<float2*>(C + (size_t)r0 * HOUT + c0) = o0;
            *reinterpret_cast<float2*>(C + (size_t)(r0 + 8) * HOUT + c0) = o1;
        }
    }
}

// ---------------------------------------------------------------------------
extern "C" void kernel_launch(void* const* d_in, const int* in_sizes, int n_in,
                              void* d_out, int out_size) {
    const float* x     = (const float*)d_in[0];   // [N, 8, 512]
    const float* gamma = (const float*)d_in[1];   // [512]
    const float* beta  = (const float*)d_in[2];   // [512]
    const float* attnW = (const float*)d_in[3];   // [1024, 1]
    // d_in[4] = attn_b: cancels in softmax.
    const float* outW  = (const float*)d_in[5];   // [512, 256]
    const float* outb  = (const float*)d_in[6];   // [256]
    float* out = (float*)d_out;                   // [N, 256]

    const int n = in_sizes[0] / (SEQ * HDIM);

    cudaFuncSetAttribute(gemm_fp16_kernel,
                         cudaFuncAttributeMaxDynamicSharedMemorySize, GEMM_SMEM);

    transpose_B_kernel<<<dim3(HOUT / 32, HDIM / 32), 256>>>(outW);
    ln_attn_v5_kernel<<<n, 256>>>(x, gamma, beta, attnW);

    dim3 grid(HOUT / BN, n / BM);
    gemm_fp16_kernel<<<grid, 256, GEMM_SMEM>>>(outb, out);
}

// round 13
// speedup vs baseline: 1.5191x; 1.0026x over previous
#include <cuda_runtime.h>
#include <cuda_fp16.h>
#include <cstdint>

#define SEQ     8
#define HDIM    512
#define HOUT    256
#define LN_EPS  1e-5f
#define MAX_ROWS 65536

// Scratch: fused (node + pooled) vectors, [N, 512], fp16.
__device__ __half g_fused[(size_t)MAX_ROWS * HDIM];
// Transposed + fp16-rounded out_W: [256, 512] (n-major, k-contiguous).
__device__ __half g_Bt[(size_t)HOUT * HDIM];

// ---------------------------------------------------------------------------
// Helpers
// ---------------------------------------------------------------------------
__device__ __forceinline__ uint32_t smem_u32(const void* p) {
    uint32_t a;
    asm("{ .reg .u64 t; cvta.to.shared.u64 t, %1; cvt.u32.u64 %0, t; }" : "=r"(a) : "l"(p));
    return a;
}

__device__ __forceinline__ void mma_fp16(float* d, const uint32_t* a, const uint32_t* b) {
    asm volatile(
        "mma.sync.aligned.m16n8k16.row.col.f32.f16.f16.f32 "
        "{%0,%1,%2,%3}, {%4,%5,%6,%7}, {%8,%9}, {%0,%1,%2,%3};"
        : "+f"(d[0]), "+f"(d[1]), "+f"(d[2]), "+f"(d[3])
        : "r"(a[0]), "r"(a[1]), "r"(a[2]), "r"(a[3]), "r"(b[0]), "r"(b[1]));
}

__device__ __forceinline__ void cp_async16(uint32_t dst, const void* src) {
    asm volatile("cp.async.cg.shared.global [%0], [%1], 16;"
                 :: "r"(dst), "l"(src) : "memory");
}
#define CP_COMMIT() asm volatile("cp.async.commit_group;" ::: "memory")
#define CP_WAIT(n)  asm volatile("cp.async.wait_group %0;" :: "n"(n) : "memory")

// ---------------------------------------------------------------------------
// Kernel A (v6): LayerNorm + attention pooling.
// Thread owns FOUR columns (float4) -> instruction count per byte halves vs
// v4. CTA = 256 threads = 2 rows, 4 warps per row. Batched reduce-scatter
// (31 shuffles for all 25 partials), cross-warp via tiny smem exchange.
// ---------------------------------------------------------------------------
__global__ __launch_bounds__(256) void ln_attn_v6_kernel(
    const float* __restrict__ x,
    const float* __restrict__ gamma,
    const float* __restrict__ beta,
    const float* __restrict__ attnW)
{
    __shared__ float s_red[2][4][26];
    __shared__ float s_k[2][8];
    __shared__ float s_K[2];

    const int tid  = threadIdx.x;
    const int w    = tid >> 5;
    const int lane = tid & 31;
    const int rloc = w >> 2;                 // 0..1
    const int slab = w & 3;                  // 0..3
    const size_t row = (size_t)blockIdx.x * 2 + rloc;
    const int c4  = slab * 32 + lane;        // float4 column 0..127
    const int col = c4 * 4;

    const float4* xr = reinterpret_cast<const float4*>(x + row * SEQ * HDIM);
    const float4 gv = *reinterpret_cast<const float4*>(gamma + col);
    const float4 wn = *reinterpret_cast<const float4*>(attnW + HDIM + col);
    float4 gw;
    gw.x = gv.x * wn.x; gw.y = gv.y * wn.y; gw.z = gv.z * wn.z; gw.w = gv.w * wn.w;

    // Phase 1: x into registers, per-position partials.
    float4 xv[SEQ];
    float vals[32];
    #pragma unroll
    for (int t = 0; t < SEQ; t++) {
        const float4 v = xr[t * (HDIM / 4) + c4];
        xv[t] = v;
        vals[t]      = (v.x + v.y) + (v.z + v.w);
        vals[8 + t]  = (v.x * v.x + v.y * v.y) + (v.z * v.z + v.w * v.w);
        vals[16 + t] = (gw.x * v.x + gw.y * v.y) + (gw.z * v.z + gw.w * v.w);
    }
    vals[24] = (gw.x + gw.y) + (gw.z + gw.w);
    #pragma unroll
    for (int j = 25; j < 32; j++) vals[j] = 0.f;

    // Batched reduce-scatter: lane l ends with warp-total of quantity l.
    #pragma unroll
    for (int bit = 16; bit >= 1; bit >>= 1) {
        #pragma unroll
        for (int j = 0; j < bit; j++) {
            const bool hi = (lane & bit) != 0;
            const float keep = hi ? vals[j + bit] : vals[j];
            const float send = hi ? vals[j] : vals[j + bit];
            vals[j] = keep + __shfl_xor_sync(0xffffffffu, send, bit);
        }
    }

    if (lane < 25) s_red[rloc][slab][lane] = vals[0];
    __syncthreads();

    // Phase 2: warp 0 -> row 0, warp 4 -> row 1. Reduce 4 slabs + softmax.
    if ((w & 3) == 0) {
        const int r = rloc;
        float v = 0.f;
        if (lane < 25) {
            #pragma unroll
            for (int sl = 0; sl < 4; sl++) v += s_red[r][sl][lane];
        }
        const int t = lane & 7;
        const float S  = __shfl_sync(0xffffffffu, v, t);
        const float Q  = __shfl_sync(0xffffffffu, v, 8 + t);
        const float P  = __shfl_sync(0xffffffffu, v, 16 + t);
        const float S1 = __shfl_sync(0xffffffffu, v, 24);

        const float m    = S * (1.f / HDIM);
        const float var  = Q * (1.f / HDIM) - m * m;
        const float rstd = rsqrtf(var + LN_EPS);

        float logit = (lane >= 1 && lane < 8) ? rstd * (P - m * S1) : -1e30f;

        float mx = logit;
        mx = fmaxf(mx, __shfl_xor_sync(0xffffffffu, mx, 1));
        mx = fmaxf(mx, __shfl_xor_sync(0xffffffffu, mx, 2));
        mx = fmaxf(mx, __shfl_xor_sync(0xffffffffu, mx, 4));
        const float e = __expf(logit - mx);
        float se = e;
        se += __shfl_xor_sync(0xffffffffu, se, 1);
        se += __shfl_xor_sync(0xffffffffu, se, 2);
        se += __shfl_xor_sync(0xffffffffu, se, 4);
        const float a = e / se;

        const float k = (lane == 0) ? rstd : a * rstd;
        float Km = k * m;
        Km += __shfl_xor_sync(0xffffffffu, Km, 1);
        Km += __shfl_xor_sync(0xffffffffu, Km, 2);
        Km += __shfl_xor_sync(0xffffffffu, Km, 4);

        if (lane < 8) s_k[r][lane] = k;
        if (lane == 0) s_K[r] = Km;
    }
    __syncthreads();

    // Phase 3: register combine, fp16 store (4 halves = 8 B).
    const float Kc = s_K[rloc];
    float4 acc = make_float4(0.f, 0.f, 0.f, 0.f);
    #pragma unroll
    for (int t = 0; t < SEQ; t++) {
        const float k = s_k[rloc][t];
        acc.x += k * xv[t].x;
        acc.y += k * xv[t].y;
        acc.z += k * xv[t].z;
        acc.w += k * xv[t].w;
    }
    const float4 bv = *reinterpret_cast<const float4*>(beta + col);
    const __half2 o0 = __floats2half2_rn(gv.x * (acc.x - Kc) + 2.f * bv.x,
                                         gv.y * (acc.y - Kc) + 2.f * bv.y);
    const __half2 o1 = __floats2half2_rn(gv.z * (acc.z - Kc) + 2.f * bv.z,
                                         gv.w * (acc.w - Kc) + 2.f * bv.w);
    uint2 o;
    o.x = *reinterpret_cast<const uint32_t*>(&o0);
    o.y = *reinterpret_cast<const uint32_t*>(&o1);
    *reinterpret_cast<uint2*>(&g_fused[row * HDIM + col]) = o;
}

// ---------------------------------------------------------------------------
// Transpose out_W [512,256] -> g_Bt [256,512] fp16.
// ---------------------------------------------------------------------------
__global__ __launch_bounds__(256) void transpose_B_kernel(const float* __restrict__ B) {
    __shared__ float tile[32][33];
    const int n0 = blockIdx.x * 32;
    const int k0 = blockIdx.y * 32;
    const int tx = threadIdx.x & 31;
    const int ty = threadIdx.x >> 5;
    #pragma unroll
    for (int i = 0; i < 32; i += 8)
        tile[ty + i][tx] = B[(size_t)(k0 + ty + i) * HOUT + n0 + tx];
    __syncthreads();
    #pragma unroll
    for (int i = 0; i < 32; i += 8) {
        g_Bt[(size_t)(n0 + ty + i) * HDIM + k0 + tx] = __float2half_rn(tile[tx][ty + i]);
    }
}

// ---------------------------------------------------------------------------
// Kernel B (v7): fp16 mma.sync GEMM — frozen from R12 (≈60 µs).
// ---------------------------------------------------------------------------
#define BM 128
#define BN 128
#define BKH 32
#define STAGES 3
#define A_STAGE_BYTES (BM * BKH * 2)
#define B_STAGE_BYTES (BN * BKH * 2)
#define STAGE_BYTES   (A_STAGE_BYTES + B_STAGE_BYTES)
#define GEMM_SMEM     (STAGES * STAGE_BYTES)
#define NCH           (HDIM / BKH)

__global__ __launch_bounds__(256, 2) void gemm_fp16_kernel(
    const float* __restrict__ bias,
    float* __restrict__ C)
{
    extern __shared__ char smem[];

    const int tid  = threadIdx.x;
    const int lane = tid & 31;
    const int wid  = tid >> 5;
    const int warp_m = wid & 3;
    const int warp_n = wid >> 2;
    const int g  = lane >> 2;
    const int tg = lane & 3;

    const int bn = blockIdx.x;
    const int bm = (int)(gridDim.y - 1) - (int)blockIdx.y;

    const __half* Ag = g_fused + (size_t)bm * BM * HDIM;
    const __half* Bg = g_Bt + (size_t)bn * BN * HDIM;

    const uint32_t smem_base = smem_u32(smem);

    const int st_row = tid >> 1;
    const int st_u   = (tid & 1) * 2;

    float acc[2][8][4];
    #pragma unroll
    for (int mt = 0; mt < 2; mt++)
        #pragma unroll
        for (int nt = 0; nt < 8; nt++)
            #pragma unroll
            for (int i = 0; i < 4; i++) acc[mt][nt][i] = 0.f;

    auto stage_chunk = [&](int kchunk, int st) {
        const uint32_t sA = smem_base + (uint32_t)(st * STAGE_BYTES);
        const uint32_t sB = sA + A_STAGE_BYTES;
        const __half* srcA = Ag + (size_t)st_row * HDIM + kchunk * BKH + st_u * 8;
        const __half* srcB = Bg + (size_t)st_row * HDIM + kchunk * BKH + st_u * 8;
        #pragma unroll
        for (int j = 0; j < 2; j++)
            cp_async16(sA + (uint32_t)(st_row * 4 + st_u + j) * 16u, srcA + j * 8);
        #pragma unroll
        for (int j = 0; j < 2; j++)
            cp_async16(sB + (uint32_t)(st_row * 4 + st_u + j) * 16u, srcB + j * 8);
    };

    stage_chunk(0, 0); CP_COMMIT();
    stage_chunk(1, 1); CP_COMMIT();

    #pragma unroll
    for (int k = 0; k < NCH; k++) {
        const int cur = k % STAGES;

        CP_WAIT(1);
        __syncthreads();

        if (k + 2 < NCH) stage_chunk(k + 2, (k + 2) % STAGES);
        CP_COMMIT();

        const char* Abuf = smem + cur * STAGE_BYTES;
        const char* Bbuf = Abuf + A_STAGE_BYTES;

        uint32_t aw[2][2][4];
        #pragma unroll
        for (int mt = 0; mt < 2; mt++) {
            #pragma unroll
            for (int h = 0; h < 2; h++) {
                const int r = warp_m * 32 + mt * 16 + g + h * 8;
                const uint4 v = *reinterpret_cast<const uint4*>(
                    Abuf + (r * 4 + tg) * 16);
                aw[mt][h][0] = v.x; aw[mt][h][1] = v.y;
                aw[mt][h][2] = v.z; aw[mt][h][3] = v.w;
            }
        }
        #pragma unroll
        for (int half = 0; half < 2; half++) {
            uint32_t bw[4][4];
            #pragma unroll
            for (int q = 0; q < 4; q++) {
                const int n = warp_n * 64 + (half * 4 + q) * 8 + g;
                const uint4 v = *reinterpret_cast<const uint4*>(
                    Bbuf + (n * 4 + tg) * 16);
                bw[q][0] = v.x; bw[q][1] = v.y; bw[q][2] = v.z; bw[q][3] = v.w;
            }
            #pragma unroll
            for (int grp = 0; grp < 2; grp++) {
                #pragma unroll
                for (int mt = 0; mt < 2; mt++) {
                    #pragma unroll
                    for (int q = 0; q < 4; q++) {
                        const int nt = half * 4 + q;
                        uint32_t a[4] = { aw[mt][0][grp * 2 + 0],
                                          aw[mt][1][grp * 2 + 0],
                                          aw[mt][0][grp * 2 + 1],
                                          aw[mt][1][grp * 2 + 1] };
                        uint32_t b[2] = { bw[q][grp * 2 + 0],
                                          bw[q][grp * 2 + 1] };
                        mma_fp16(acc[mt][nt], a, b);
                    }
                }
            }
        }
    }

    const int row_base = bm * BM + warp_m * 32;
    const int col_base = bn * BN + warp_n * 64;
    #pragma unroll
    for (int mt = 0; mt < 2; mt++) {
        #pragma unroll
        for (int nt = 0; nt < 8; nt++) {
            const int r0 = row_base + mt * 16 + g;
            const int c0 = col_base + nt * 8 + 2 * tg;
            const float2 bb = *reinterpret_cast<const float2*>(bias + c0);
            float2 o0, o1;
            o0.x = fmaxf(acc[mt][nt][0] + bb.x, 0.f);
            o0.y = fmaxf(acc[mt][nt][1] + bb.y, 0.f);
            o1.x = fmaxf(acc[mt][nt][2] + bb.x, 0.f);
            o1.y = fmaxf(acc[mt][nt][3] + bb.y, 0.f);
            *reinterpret_cast<float2*>(C + (size_t)r0 * HOUT + c0) = o0;
            *reinterpret_cast<float2*>(C + (size_t)(r0 + 8) * HOUT + c0) = o1;
        }
    }
}

// ---------------------------------------------------------------------------
extern "C" void kernel_launch(void* const* d_in, const int* in_sizes, int n_in,
                              void* d_out, int out_size) {
    const float* x     = (const float*)d_in[0];   // [N, 8, 512]
    const float* gamma = (const float*)d_in[1];   // [512]
    const float* beta  = (const float*)d_in[2];   // [512]
    const float* attnW = (const float*)d_in[3];   // [1024, 1]
    // d_in[4] = attn_b: cancels in softmax.
    const float* outW  = (const float*)d_in[5];   // [512, 256]
    const float* outb  = (const float*)d_in[6];   // [256]
    float* out = (float*)d_out;                   // [N, 256]

    const int n = in_sizes[0] / (SEQ * HDIM);

    cudaFuncSetAttribute(gemm_fp16_kernel,
                         cudaFuncAttributeMaxDynamicSharedMemorySize, GEMM_SMEM);

    transpose_B_kernel<<<dim3(HOUT / 32, HDIM / 32), 256>>>(outW);
    ln_attn_v6_kernel<<<n / 2, 256>>>(x, gamma, beta, attnW);

    dim3 grid(HOUT / BN, n / BM);
    gemm_fp16_kernel<<<grid, 256, GEMM_SMEM>>>(outb, out);
}